// round 1
// baseline (speedup 1.0000x reference)
#include <cuda_runtime.h>

#define N_NODES 2048
#define FDIM 256
#define HID 64
#define TPL 10

// ---------------- device scratch (no allocations allowed) ----------------
__device__ float g_h3[FDIM];
__device__ float g_trig[N_NODES * FDIM];
__device__ float g_pa[N_NODES * HID];   // pa + eb1 folded in
__device__ float g_pb[N_NODES * HID];

// ---------------- kernel 1: proto -> 3-layer MLP -> h3 ----------------
// The reference's A @ X is identity on identical-row matrices, so the GCN
// collapses to a single vector MLP.
__global__ void k_prep(const float* __restrict__ clean, const int* __restrict__ sel,
                       const float* __restrict__ w1, const float* __restrict__ b1,
                       const float* __restrict__ w2, const float* __restrict__ b2,
                       const float* __restrict__ w3, const float* __restrict__ b3) {
    __shared__ float proto[FDIM];
    __shared__ float h1[HID], h2[HID];
    int t = threadIdx.x;   // 256 threads

    float s = 0.f;
    #pragma unroll
    for (int r = 0; r < TPL; r++)
        s += clean[(long long)sel[r] * FDIM + t];
    proto[t] = s * 0.1f;
    __syncthreads();

    if (t < HID) {
        float a0 = b1[t], a1 = 0.f;
        #pragma unroll 8
        for (int d = 0; d < FDIM; d += 2) {
            a0 = fmaf(proto[d],     w1[d * HID + t],       a0);
            a1 = fmaf(proto[d + 1], w1[(d + 1) * HID + t], a1);
        }
        h1[t] = fmaxf(a0 + a1, 0.f);
    }
    __syncthreads();

    if (t < HID) {
        float a0 = b2[t], a1 = 0.f;
        #pragma unroll 8
        for (int d = 0; d < HID; d += 2) {
            a0 = fmaf(h1[d],     w2[d * HID + t],       a0);
            a1 = fmaf(h1[d + 1], w2[(d + 1) * HID + t], a1);
        }
        h2[t] = fmaxf(a0 + a1, 0.f);
    }
    __syncthreads();

    {
        float a0 = b3[t], a1 = 0.f;
        #pragma unroll 8
        for (int d = 0; d < HID; d += 2) {
            a0 = fmaf(h2[d],     w3[d * FDIM + t],       a0);
            a1 = fmaf(h2[d + 1], w3[(d + 1) * FDIM + t], a1);
        }
        float x = a0 + a1;
        g_h3[t] = 1.f / (1.f + __expf(-x));
    }
}

// ---------------- kernel 2: build trig, write to out + scratch ----------------
// grid: 512 blocks x 256 threads, one float4 per thread (2048*256 floats total)
__global__ void k_trig(const float* __restrict__ noise, float* __restrict__ out) {
    int idx4 = blockIdx.x * 256 + threadIdx.x;   // float4 index
    int i  = idx4 >> 6;                          // row (64 float4 per row)
    int d4 = idx4 & 63;
    float4 v = ((const float4*)g_h3)[d4];
    if (i >= TPL) {
        float4 n = ((const float4*)noise)[(i - TPL) * 64 + d4];
        v.x = fmaf(0.1f, n.x, v.x);
        v.y = fmaf(0.1f, n.y, v.y);
        v.z = fmaf(0.1f, n.z, v.z);
        v.w = fmaf(0.1f, n.w, v.w);
    }
    ((float4*)out)[idx4]    = v;
    ((float4*)g_trig)[idx4] = v;
}

// ---------------- kernel 3: pa = trig@w1a + eb1, pb = trig@w1b ----------------
// grid: (64 row-tiles of 32 rows, 4 col-tiles of 32 cols out of 128)
// 256 threads; thread computes 4 rows x 1 col.
__global__ void k_papb(const float* __restrict__ ew1, const float* __restrict__ eb1) {
    __shared__ float trig_s[32][FDIM];   // 32 KB
    int t = threadIdx.x;
    int row0 = blockIdx.x * 32;
    int c = blockIdx.y * 32 + (t & 31);  // 0..127 : c<64 -> pa col c, else pb col c-64
    int ry = t >> 5;                     // 0..7

    // load 32x256 trig tile, float4-coalesced
    #pragma unroll
    for (int m = 0; m < 8; m++) {
        int q = t + m * 256;             // float4 index in tile (2048 total)
        int r = q >> 6, d4 = q & 63;
        ((float4*)&trig_s[r][0])[d4] = ((const float4*)g_trig)[(row0 + r) * 64 + d4];
    }
    __syncthreads();

    int k = c & 63;
    const float* wptr = ew1 + (c < HID ? 0 : FDIM * HID) + k;   // stride HID per d
    float init = (c < HID) ? eb1[c] : 0.f;
    float acc0 = init, acc1 = init, acc2 = init, acc3 = init;

    #pragma unroll 8
    for (int d = 0; d < FDIM; d++) {
        float w = wptr[d * HID];
        acc0 = fmaf(trig_s[ry     ][d], w, acc0);
        acc1 = fmaf(trig_s[ry +  8][d], w, acc1);
        acc2 = fmaf(trig_s[ry + 16][d], w, acc2);
        acc3 = fmaf(trig_s[ry + 24][d], w, acc3);
    }

    float* dst = (c < HID) ? g_pa : g_pb;
    int cc = k;
    dst[(row0 + ry     ) * HID + cc] = acc0;
    dst[(row0 + ry +  8) * HID + cc] = acc1;
    dst[(row0 + ry + 16) * HID + cc] = acc2;
    dst[(row0 + ry + 24) * HID + cc] = acc3;
}

// ---------------- kernel 4: edge probs over upper triangle ----------------
// grid (32, 32) of 64x64 pair tiles; blocks with bj < bi exit immediately.
// 256 threads (16x16), 4x4 register blocking per thread.
#define PAD 66
__global__ void k_edge(const float* __restrict__ ew2, const float* __restrict__ eb2,
                       float* __restrict__ out_e) {
    int bi = blockIdx.y, bj = blockIdx.x;
    if (bj < bi) return;

    __shared__ float pa_s[64 * PAD];
    __shared__ float pb_s[64 * PAD];
    __shared__ float w2_s[HID];

    int t = threadIdx.x;
    int tx = t & 15, ty = t >> 4;
    int i0 = bi * 64, j0 = bj * 64;

    // load 64x64 pa/pb tiles as float2, store with stride-66 padding
    #pragma unroll
    for (int m = 0; m < 8; m++) {
        int q = t + m * 256;            // float2 index (2048 = 64 rows * 32)
        int r = q >> 5, k2 = q & 31;
        float2 va = ((const float2*)g_pa)[(i0 + r) * 32 + k2];
        float2 vb = ((const float2*)g_pb)[(j0 + r) * 32 + k2];
        *(float2*)&pa_s[r * PAD + 2 * k2] = va;
        *(float2*)&pb_s[r * PAD + 2 * k2] = vb;
    }
    if (t < HID) w2_s[t] = ew2[t];
    __syncthreads();

    float acc[4][4] = {};

    #pragma unroll 4
    for (int k = 0; k < HID; k++) {
        float w = w2_s[k];
        float a[4], b[4];
        a[0] = pa_s[(ty     ) * PAD + k];
        a[1] = pa_s[(ty + 16) * PAD + k];
        a[2] = pa_s[(ty + 32) * PAD + k];
        a[3] = pa_s[(ty + 48) * PAD + k];
        b[0] = pb_s[(tx     ) * PAD + k];
        b[1] = pb_s[(tx + 16) * PAD + k];
        b[2] = pb_s[(tx + 32) * PAD + k];
        b[3] = pb_s[(tx + 48) * PAD + k];
        #pragma unroll
        for (int r = 0; r < 4; r++)
            #pragma unroll
            for (int c = 0; c < 4; c++)
                acc[r][c] = fmaf(fmaxf(a[r] + b[c], 0.f), w, acc[r][c]);
    }

    float bias = eb2[0];
    #pragma unroll
    for (int r = 0; r < 4; r++) {
        int i = i0 + ty + 16 * r;
        int rowoff = i * (N_NODES - 1) - ((i * (i - 1)) >> 1);   // triu offset of row i
        #pragma unroll
        for (int c = 0; c < 4; c++) {
            int j = j0 + tx + 16 * c;
            if (j > i) {
                float x = acc[r][c] + bias;
                out_e[rowoff + (j - i - 1)] = 1.f / (1.f + __expf(-x));
            }
        }
    }
}

// ---------------- launch ----------------
extern "C" void kernel_launch(void* const* d_in, const int* in_sizes, int n_in,
                              void* d_out, int out_size) {
    const float* clean = (const float*)d_in[0];
    const int*   sel   = (const int*)  d_in[1];
    const float* noise = (const float*)d_in[2];
    const float* g1w = (const float*)d_in[3];
    const float* g1b = (const float*)d_in[4];
    const float* g2w = (const float*)d_in[5];
    const float* g2b = (const float*)d_in[6];
    const float* g3w = (const float*)d_in[7];
    const float* g3b = (const float*)d_in[8];
    const float* ew1 = (const float*)d_in[9];
    const float* eb1 = (const float*)d_in[10];
    const float* ew2 = (const float*)d_in[11];
    const float* eb2 = (const float*)d_in[12];
    float* out = (float*)d_out;

    k_prep<<<1, 256>>>(clean, sel, g1w, g1b, g2w, g2b, g3w, g3b);
    k_trig<<<512, 256>>>(noise, out);
    k_papb<<<dim3(64, 4), 256>>>(ew1, eb1);
    k_edge<<<dim3(32, 32), 256>>>(ew2, eb2, out + N_NODES * FDIM);
}

// round 2
// speedup vs baseline: 1.1854x; 1.1854x over previous
#include <cuda_runtime.h>

#define N_NODES 2048
#define FDIM 256
#define HID 64
#define TPL 10

typedef unsigned long long ull;

// ---------------- device scratch ----------------
__device__ float4 g_h3v[FDIM / 4];
__device__ float g_pa[N_NODES * HID];   // pa + eb1 folded in
__device__ float g_pb[N_NODES * HID];

// ---------------- f32x2 helpers (Blackwell packed fp32) ----------------
__device__ __forceinline__ ull add2(ull a, ull b) {
    ull r; asm("add.rn.f32x2 %0, %1, %2;" : "=l"(r) : "l"(a), "l"(b)); return r;
}
__device__ __forceinline__ ull fma2(ull a, ull b, ull c) {
    ull r; asm("fma.rn.f32x2 %0, %1, %2, %3;" : "=l"(r) : "l"(a), "l"(b), "l"(c)); return r;
}
__device__ __forceinline__ ull relu2(ull x) {
    float lo, hi;
    asm("mov.b64 {%0, %1}, %2;" : "=f"(lo), "=f"(hi) : "l"(x));
    lo = fmaxf(lo, 0.f);
    hi = fmaxf(hi, 0.f);
    ull r; asm("mov.b64 %0, {%1, %2};" : "=l"(r) : "f"(lo), "f"(hi)); return r;
}
__device__ __forceinline__ ull pack2(float lo, float hi) {
    ull r; asm("mov.b64 %0, {%1, %2};" : "=l"(r) : "f"(lo), "f"(hi)); return r;
}
__device__ __forceinline__ float hsum2(ull x) {
    float lo, hi;
    asm("mov.b64 {%0, %1}, %2;" : "=f"(lo), "=f"(hi) : "l"(x));
    return lo + hi;
}

// ---------------- kernel 1: proto -> 3-layer MLP -> h3 (all threads busy) ----
__global__ void k_prep(const float* __restrict__ clean, const int* __restrict__ sel,
                       const float* __restrict__ w1, const float* __restrict__ b1,
                       const float* __restrict__ w2, const float* __restrict__ b2,
                       const float* __restrict__ w3, const float* __restrict__ b3) {
    __shared__ float proto[FDIM];
    __shared__ float part[4][HID];
    __shared__ float h1[HID], h2[HID];
    int t = threadIdx.x;   // 256 threads

    float s = 0.f;
    #pragma unroll
    for (int r = 0; r < TPL; r++)
        s += clean[(long long)sel[r] * FDIM + t];
    proto[t] = s * 0.1f;
    __syncthreads();

    // layer 1: 256x64, 4-way split over d
    {
        int h = t & 63, seg = t >> 6;
        const float* w = w1 + seg * 64 * HID + h;
        float a0 = 0.f, a1 = 0.f;
        #pragma unroll 8
        for (int d = 0; d < 64; d += 2) {
            a0 = fmaf(proto[seg * 64 + d],     w[d * HID],       a0);
            a1 = fmaf(proto[seg * 64 + d + 1], w[(d + 1) * HID], a1);
        }
        part[seg][h] = a0 + a1;
    }
    __syncthreads();
    if (t < HID)
        h1[t] = fmaxf(part[0][t] + part[1][t] + part[2][t] + part[3][t] + b1[t], 0.f);
    __syncthreads();

    // layer 2: 64x64, 4-way split over d
    {
        int h = t & 63, seg = t >> 6;
        const float* w = w2 + seg * 16 * HID + h;
        float a0 = 0.f;
        #pragma unroll
        for (int d = 0; d < 16; d++)
            a0 = fmaf(h1[seg * 16 + d], w[d * HID], a0);
        part[seg][h] = a0;
    }
    __syncthreads();
    if (t < HID)
        h2[t] = fmaxf(part[0][t] + part[1][t] + part[2][t] + part[3][t] + b2[t], 0.f);
    __syncthreads();

    // layer 3: 64x256, one output per thread
    {
        float a0 = 0.f, a1 = 0.f;
        #pragma unroll 8
        for (int d = 0; d < HID; d += 2) {
            a0 = fmaf(h2[d],     w3[d * FDIM + t],       a0);
            a1 = fmaf(h2[d + 1], w3[(d + 1) * FDIM + t], a1);
        }
        float x = a0 + a1 + b3[t];
        ((float*)g_h3v)[t] = 1.f / (1.f + __expf(-x));
    }
}

// ---------------- kernel 2: fused trig build + pa/pb GEMM ----------------
// grid (64 row-tiles of 32 rows, 2 col-halves). Builds the trig tile in smem
// from h3 + 0.1*noise (writes it to out once, on by==0), then computes
// pa (+eb1) or pb for its 64-column half with d-packed fma2.
#define TPAD 260   // 1040 B row stride: 16B-aligned for float4, fine for bcast ull
__global__ void k_papb(const float* __restrict__ noise,
                       const float* __restrict__ ew1, const float* __restrict__ eb1,
                       float* __restrict__ out) {
    __shared__ float trig_s[32][TPAD];
    int t = threadIdx.x;
    int row0 = blockIdx.x * 32;
    int ch = blockIdx.y;                 // 0 -> pa (w1a), 1 -> pb (w1b)

    // Phase A: build 32x256 trig tile
    #pragma unroll
    for (int m = 0; m < 8; m++) {
        int q = t + m * 256;             // float4 index (2048 total)
        int r = q >> 6, d4 = q & 63;
        float4 v = g_h3v[d4];
        int row = row0 + r;
        if (row >= TPL) {
            float4 n = ((const float4*)noise)[(row - TPL) * 64 + d4];
            v.x = fmaf(0.1f, n.x, v.x);
            v.y = fmaf(0.1f, n.y, v.y);
            v.z = fmaf(0.1f, n.z, v.z);
            v.w = fmaf(0.1f, n.w, v.w);
        }
        ((float4*)&trig_s[r][0])[d4] = v;
        if (ch == 0) ((float4*)out)[row * 64 + d4] = v;
    }
    __syncthreads();

    // Phase B: 32x256 @ 256x64 GEMM, d-packed. thread: col cc, 8 rows.
    int cc = t & 63;
    int rr = t >> 6;                     // 0..3 -> rows rr*8 .. rr*8+7
    const float* wbase = ew1 + ch * (FDIM * HID) + cc;

    ull acc[8] = {0, 0, 0, 0, 0, 0, 0, 0};
    #pragma unroll 2
    for (int d2 = 0; d2 < FDIM / 2; d2++) {
        float w0 = wbase[(2 * d2) * HID];
        float w1 = wbase[(2 * d2 + 1) * HID];
        ull wp = pack2(w0, w1);
        #pragma unroll
        for (int m = 0; m < 8; m++) {
            ull a2 = *(const ull*)&trig_s[rr * 8 + m][2 * d2];
            acc[m] = fma2(a2, wp, acc[m]);
        }
    }

    float bias = (ch == 0) ? eb1[cc] : 0.f;
    float* dst = (ch == 0) ? g_pa : g_pb;
    #pragma unroll
    for (int m = 0; m < 8; m++)
        dst[(row0 + rr * 8 + m) * HID + cc] = hsum2(acc[m]) + bias;
}

// ---------------- kernel 3: edge probs, k-packed f32x2 ----------------
// grid = 528 linearized upper-triangle 64x64 tiles. 256 threads (16x16),
// 4x4 register blocking, accumulators packed over k.
#define PAD 66   // 264 B row stride, 8B-aligned, odd in 8B units -> conflict-free
__global__ void k_edge(const float* __restrict__ ew2, const float* __restrict__ eb2,
                       float* __restrict__ out_e) {
    int L = blockIdx.x;
    int bi = (int)((65.0f - sqrtf(4225.0f - 8.0f * (float)L)) * 0.5f);
    while ((bi + 1) * (65 - (bi + 1)) / 2 <= L) bi++;
    while (bi * (65 - bi) / 2 > L) bi--;
    int bj = bi + (L - bi * (65 - bi) / 2);

    __shared__ float pa_s[64 * PAD];
    __shared__ float pb_s[64 * PAD];
    __shared__ ull w2_s[HID / 2];

    int t = threadIdx.x;
    int tx = t & 15, ty = t >> 4;
    int i0 = bi * 64, j0 = bj * 64;

    #pragma unroll
    for (int m = 0; m < 8; m++) {
        int q = t + m * 256;             // float2 index (2048 = 64 rows * 32)
        int r = q >> 5, k2 = q & 31;
        float2 va = ((const float2*)g_pa)[(i0 + r) * 32 + k2];
        float2 vb = ((const float2*)g_pb)[(j0 + r) * 32 + k2];
        *(float2*)&pa_s[r * PAD + 2 * k2] = va;
        *(float2*)&pb_s[r * PAD + 2 * k2] = vb;
    }
    if (t < HID / 2) w2_s[t] = pack2(ew2[2 * t], ew2[2 * t + 1]);
    __syncthreads();

    ull acc[4][4] = {};

    #pragma unroll 4
    for (int k2 = 0; k2 < HID / 2; k2++) {
        ull w = w2_s[k2];
        ull a2[4], b2[4];
        #pragma unroll
        for (int r = 0; r < 4; r++)
            a2[r] = *(const ull*)&pa_s[(ty + 16 * r) * PAD + 2 * k2];
        #pragma unroll
        for (int c = 0; c < 4; c++)
            b2[c] = *(const ull*)&pb_s[(tx + 16 * c) * PAD + 2 * k2];
        #pragma unroll
        for (int r = 0; r < 4; r++)
            #pragma unroll
            for (int c = 0; c < 4; c++)
                acc[r][c] = fma2(relu2(add2(a2[r], b2[c])), w, acc[r][c]);
    }

    float bias = eb2[0];
    #pragma unroll
    for (int r = 0; r < 4; r++) {
        int i = i0 + ty + 16 * r;
        int rowoff = i * (N_NODES - 1) - ((i * (i - 1)) >> 1);
        #pragma unroll
        for (int c = 0; c < 4; c++) {
            int j = j0 + tx + 16 * c;
            if (j > i) {
                float x = hsum2(acc[r][c]) + bias;
                out_e[rowoff + (j - i - 1)] = 1.f / (1.f + __expf(-x));
            }
        }
    }
}

// ---------------- launch ----------------
extern "C" void kernel_launch(void* const* d_in, const int* in_sizes, int n_in,
                              void* d_out, int out_size) {
    const float* clean = (const float*)d_in[0];
    const int*   sel   = (const int*)  d_in[1];
    const float* noise = (const float*)d_in[2];
    const float* g1w = (const float*)d_in[3];
    const float* g1b = (const float*)d_in[4];
    const float* g2w = (const float*)d_in[5];
    const float* g2b = (const float*)d_in[6];
    const float* g3w = (const float*)d_in[7];
    const float* g3b = (const float*)d_in[8];
    const float* ew1 = (const float*)d_in[9];
    const float* eb1 = (const float*)d_in[10];
    const float* ew2 = (const float*)d_in[11];
    const float* eb2 = (const float*)d_in[12];
    float* out = (float*)d_out;

    k_prep<<<1, 256>>>(clean, sel, g1w, g1b, g2w, g2b, g3w, g3b);
    k_papb<<<dim3(64, 2), 256>>>(noise, ew1, eb1, out);
    k_edge<<<528, 256>>>(ew2, eb2, out + N_NODES * FDIM);
}